// round 11
// baseline (speedup 1.0000x reference)
#include <cuda_runtime.h>
#include <cstdint>
#include <math.h>

#define N_NODES   100000
#define N_EDGES   200000
#define NNZ       2000000
#define HID       32
#define K_KEEP    1000000
#define NTH       256

// ---------------- device scratch (no allocations allowed) ----------------
__device__ __align__(16) float g_xa[N_NODES * HID];
__device__ __align__(16) float g_xb[N_NODES * HID];
__device__ __align__(16) float g_eb[N_EDGES * HID];
__device__ int      g_cnt[N_EDGES];
__device__ float    g_sum_p[N_EDGES];
__device__ float    g_sum_s[N_EDGES];
__device__ unsigned g_hist0[2048];
__device__ unsigned g_hist1[2048];
__device__ unsigned g_h2[1024];
__device__ unsigned g_h3[1024];
__device__ unsigned g_h4[2048];

// ---------------- shared-mem scan + threshold-bucket pick ----------------
// sA holds histogram (n bins). Finds bucket where (desc? suffix : prefix)
// cumulative first reaches rank. Deterministic for identical inputs.
__device__ void pick_bucket(unsigned* sA, unsigned* sB, int n, int rank, bool desc,
                            int* ri, int* rr, int* rn) {
    unsigned *in = sA, *out = sB;
    for (int off = 1; off < n; off <<= 1) {
        for (int i = threadIdx.x; i < n; i += NTH) {
            unsigned add = desc ? ((i + off < n) ? in[i + off] : 0u)
                                : ((i >= off) ? in[i - off] : 0u);
            out[i] = in[i] + add;
        }
        __syncthreads();
        unsigned* t = in; in = out; out = t;
    }
    for (int i = threadIdx.x; i < n; i += NTH) {
        unsigned adj = desc ? ((i + 1 < n) ? in[i + 1] : 0u)
                            : ((i > 0) ? in[i - 1] : 0u);
        if ((int)in[i] >= rank && (int)adj < rank) {
            *ri = i; *rr = rank - (int)adj; *rn = (int)(in[i] - adj);
        }
    }
    __syncthreads();
}

__device__ __forceinline__ void do_pick(const unsigned* gh, int n, int rank, bool desc,
                                        unsigned* sA, unsigned* sB,
                                        int* ri, int* rr, int* rn) {
    for (int i = threadIdx.x; i < n; i += NTH) sA[i] = gh[i];
    __syncthreads();
    pick_bucket(sA, sB, n, rank, desc, ri, rr, rn);
}

// ---------------- k_pre: zero all small state ----------------
__global__ void k_pre() {
    int tid = blockIdx.x * blockDim.x + threadIdx.x;
    int nt  = gridDim.x * blockDim.x;
    for (int i = tid; i < N_EDGES; i += nt) {
        g_cnt[i] = 0; g_sum_p[i] = 0.0f; g_sum_s[i] = 0.0f;
    }
    for (int i = tid; i < 2048; i += nt) { g_hist0[i] = 0u; g_hist1[i] = 0u; g_h4[i] = 0u; }
    for (int i = tid; i < 1024; i += nt) { g_h2[i] = 0u; g_h3[i] = 0u; }
}

// ---------------- k_init: proj (0..511) | zero eb (512..639) | count E (640..767) ----------------
#define PROJ_BLKS 512
#define ZERO_BLKS 128
#define CNT_BLKS  128
__global__ void k_init(const float* __restrict__ x,
                       const float* __restrict__ W1,
                       const float* __restrict__ b1,
                       const int* __restrict__ E) {
    int b = blockIdx.x;
    if (b < PROJ_BLKS) {
        __shared__ float sW[128 * 32];
        for (int i = threadIdx.x; i < 128 * 32; i += blockDim.x) sW[i] = W1[i];
        __syncthreads();
        int lane = threadIdx.x & 31;
        int warp = threadIdx.x >> 5;
        float bb = b1[lane];
        for (int row = b * 8 + warp; row < N_NODES; row += PROJ_BLKS * 8) {
            float x0 = x[row * 64 + lane];
            float x1 = x[row * 64 + 32 + lane];
            float aa = bb, ab = 0.0f;
#pragma unroll
            for (int k = 0; k < 32; k++) {
                float xv = __shfl_sync(0xffffffffu, x0, k);
                aa += xv * sW[k * 32 + lane];
                ab += xv * sW[(64 + k) * 32 + lane];
            }
#pragma unroll
            for (int k = 0; k < 32; k++) {
                float xv = __shfl_sync(0xffffffffu, x1, k);
                aa += xv * sW[(32 + k) * 32 + lane];
                ab += xv * sW[(96 + k) * 32 + lane];
            }
            g_xa[row * 32 + lane] = aa;
            g_xb[row * 32 + lane] = ab;
        }
    } else if (b < PROJ_BLKS + ZERO_BLKS) {
        int tid = (b - PROJ_BLKS) * blockDim.x + threadIdx.x;
        int nt  = ZERO_BLKS * blockDim.x;
        float4 z4 = make_float4(0.f, 0.f, 0.f, 0.f);
        float4* eb4 = reinterpret_cast<float4*>(g_eb);
        for (int i = tid; i < N_EDGES * HID / 4; i += nt) eb4[i] = z4;
    } else {
        int tid = (b - PROJ_BLKS - ZERO_BLKS) * blockDim.x + threadIdx.x;
        int nt  = CNT_BLKS * blockDim.x;
        for (int t = tid; t < NNZ / 4; t += nt) {
            int4 e4 = reinterpret_cast<const int4*>(E)[t];
            atomicAdd(&g_cnt[e4.x], 1);
            atomicAdd(&g_cnt[e4.y], 1);
            atomicAdd(&g_cnt[e4.z], 1);
            atomicAdd(&g_cnt[e4.w], 1);
        }
    }
}

// ---------------- k_scatter: 8 lanes / nnz, one red.v4 each ----------------
__global__ void k_scatter(const int* __restrict__ V, const int* __restrict__ E) {
    int tid = blockIdx.x * blockDim.x + threadIdx.x;
    int g   = tid >> 3;
    int sub = tid & 7;
    if (g >= NNZ) return;
    int v = V[g], e = E[g];
    float4 val = *reinterpret_cast<const float4*>(&g_xb[v * 32 + sub * 4]);
    float* dst = &g_eb[e * 32 + sub * 4];
    asm volatile("red.global.add.v4.f32 [%0], {%1,%2,%3,%4};"
                 :: "l"(dst), "f"(val.x), "f"(val.y), "f"(val.z), "f"(val.w)
                 : "memory");
}

// ---------------- k_logits: 4 lanes / nnz + fused phase-0 histogram ----------------
// grid = NNZ*4/256 = 31250 exactly: no tail, every thread active (match_any safe)
__global__ void k_logits(const int* __restrict__ V, const int* __restrict__ E,
                         const float* __restrict__ W2, const float* __restrict__ b2,
                         float* __restrict__ out_probs) {
    int tid = blockIdx.x * blockDim.x + threadIdx.x;
    int g   = tid >> 2;
    int sub = tid & 3;
    int lane = threadIdx.x & 31;
    int v = V[g], e = E[g];
    int c = g_cnt[e];
    float ic = 1.0f / (float)(c > 1 ? c : 1);
    const float4* pa = reinterpret_cast<const float4*>(&g_xa[v * 32]) + sub * 2;
    const float4* pm = reinterpret_cast<const float4*>(&g_eb[e * 32]) + sub * 2;
    const float4* pw = reinterpret_cast<const float4*>(W2) + sub * 2;
    float4 a0 = pa[0], a1 = pa[1];
    float4 m0 = pm[0], m1 = pm[1];
    float4 w0 = pw[0], w1 = pw[1];
    float part =
        fmaxf(a0.x + m0.x * ic, 0.0f) * w0.x +
        fmaxf(a0.y + m0.y * ic, 0.0f) * w0.y +
        fmaxf(a0.z + m0.z * ic, 0.0f) * w0.z +
        fmaxf(a0.w + m0.w * ic, 0.0f) * w0.w +
        fmaxf(a1.x + m1.x * ic, 0.0f) * w1.x +
        fmaxf(a1.y + m1.y * ic, 0.0f) * w1.y +
        fmaxf(a1.z + m1.z * ic, 0.0f) * w1.z +
        fmaxf(a1.w + m1.w * ic, 0.0f) * w1.w;
    part += __shfl_xor_sync(0xffffffffu, part, 2);
    part += __shfl_xor_sync(0xffffffffu, part, 1);
    if (sub == 0) {
        float z = part + b2[0];
        float p = 1.0f / (1.0f + __expf(-z));
        out_probs[g] = p;
        asm volatile("red.global.add.f32 [%0], %1;" :: "l"(&g_sum_p[e]), "f"(p) : "memory");
        // warp-aggregated phase-0 histogram (8 participating lanes: 0,4,...,28)
        unsigned bin = __float_as_uint(p) >> 21;
        unsigned peers = __match_any_sync(0x11111111u, bin);
        int leader = __ffs(peers) - 1;
        if (lane == leader) atomicAdd(&g_hist0[bin], (unsigned)__popc(peers));
    }
}

// ---------------- k_h1: pick0 -> p1; filtered hist1 pass ----------------
__global__ void k_h1(const float* __restrict__ probs) {
    __shared__ unsigned sA[2048], sB[2048];
    __shared__ int s_ri, s_rr, s_rn;
    do_pick(g_hist0, 2048, K_KEEP, true, sA, sB, &s_ri, &s_rr, &s_rn);
    unsigned p1 = (unsigned)s_ri;
    for (int i = threadIdx.x; i < 2048; i += NTH) sA[i] = 0u;
    __syncthreads();
    int tid = blockIdx.x * blockDim.x + threadIdx.x;
    int nt  = gridDim.x * blockDim.x;
    for (int t = tid; t < NNZ / 4; t += nt) {
        float4 p4 = reinterpret_cast<const float4*>(probs)[t];
        float pv[4] = {p4.x, p4.y, p4.z, p4.w};
#pragma unroll
        for (int j = 0; j < 4; j++) {
            unsigned bits = __float_as_uint(pv[j]);
            if ((bits >> 21) == p1) atomicAdd(&sA[(bits >> 10) & 2047u], 1u);
        }
    }
    __syncthreads();
    for (int i = threadIdx.x; i < 2048; i += NTH) {
        unsigned v = sA[i];
        if (v) atomicAdd(&g_hist1[i], v);
    }
}

// ---------------- k_h2: picks0-1 -> p2; filtered h2 pass ----------------
__global__ void k_h2(const float* __restrict__ probs) {
    __shared__ unsigned sA[2048], sB[2048];
    __shared__ int s_ri, s_rr, s_rn;
    do_pick(g_hist0, 2048, K_KEEP, true, sA, sB, &s_ri, &s_rr, &s_rn);
    unsigned p1 = (unsigned)s_ri;  int rank1 = s_rr;
    do_pick(g_hist1, 2048, rank1, true, sA, sB, &s_ri, &s_rr, &s_rn);
    unsigned p2 = (p1 << 11) | (unsigned)s_ri;
    for (int i = threadIdx.x; i < 1024; i += NTH) sA[i] = 0u;
    __syncthreads();
    int tid = blockIdx.x * blockDim.x + threadIdx.x;
    int nt  = gridDim.x * blockDim.x;
    for (int t = tid; t < NNZ / 4; t += nt) {
        float4 p4 = reinterpret_cast<const float4*>(probs)[t];
        float pv[4] = {p4.x, p4.y, p4.z, p4.w};
#pragma unroll
        for (int j = 0; j < 4; j++) {
            unsigned bits = __float_as_uint(pv[j]);
            if ((bits >> 10) == p2) atomicAdd(&sA[bits & 1023u], 1u);
        }
    }
    __syncthreads();
    for (int i = threadIdx.x; i < 1024; i += NTH) {
        unsigned v = sA[i];
        if (v) atomicAdd(&g_h2[i], v);
    }
}

// prologue shared by h3/h4/mask: picks 0..2
struct Sel2 { unsigned T; int skip; int rank3; };
__device__ __forceinline__ Sel2 picks012(unsigned* sA, unsigned* sB,
                                         int* ri, int* rr, int* rn) {
    do_pick(g_hist0, 2048, K_KEEP, true, sA, sB, ri, rr, rn);
    unsigned p1 = (unsigned)*ri;  int rank1 = *rr;
    do_pick(g_hist1, 2048, rank1, true, sA, sB, ri, rr, rn);
    unsigned p2 = (p1 << 11) | (unsigned)*ri;  int rank2 = *rr;
    do_pick(g_h2, 1024, rank2, true, sA, sB, ri, rr, rn);
    Sel2 s;
    s.T = (p2 << 10) | (unsigned)*ri;
    s.rank3 = *rr;
    s.skip = (*rr >= *rn) ? 1 : 0;
    return s;
}

// ---------------- k_h3: ties' index-high histogram (rare path) ----------------
__global__ void k_h3(const float* __restrict__ probs) {
    __shared__ unsigned sA[2048], sB[2048];
    __shared__ int s_ri, s_rr, s_rn;
    Sel2 s = picks012(sA, sB, &s_ri, &s_rr, &s_rn);
    if (s.skip) return;
    for (int i = threadIdx.x; i < 1024; i += NTH) sA[i] = 0u;
    __syncthreads();
    int tid = blockIdx.x * blockDim.x + threadIdx.x;
    int nt  = gridDim.x * blockDim.x;
    for (int t = tid; t < NNZ / 4; t += nt) {
        float4 p4 = reinterpret_cast<const float4*>(probs)[t];
        float pv[4] = {p4.x, p4.y, p4.z, p4.w};
#pragma unroll
        for (int j = 0; j < 4; j++) {
            unsigned bits = __float_as_uint(pv[j]);
            if (bits == s.T) atomicAdd(&sA[(unsigned)(4 * t + j) >> 11], 1u);
        }
    }
    __syncthreads();
    for (int i = threadIdx.x; i < 1024; i += NTH) {
        unsigned v = sA[i];
        if (v) atomicAdd(&g_h3[i], v);
    }
}

// ---------------- k_h4: ties' index-low histogram (rare path) ----------------
__global__ void k_h4(const float* __restrict__ probs) {
    __shared__ unsigned sA[2048], sB[2048];
    __shared__ int s_ri, s_rr, s_rn;
    Sel2 s = picks012(sA, sB, &s_ri, &s_rr, &s_rn);
    if (s.skip) return;
    do_pick(g_h3, 1024, s.rank3, false, sA, sB, &s_ri, &s_rr, &s_rn);
    int ib = s_ri;
    for (int i = threadIdx.x; i < 2048; i += NTH) sA[i] = 0u;
    __syncthreads();
    int tid = blockIdx.x * blockDim.x + threadIdx.x;
    int nt  = gridDim.x * blockDim.x;
    for (int t = tid; t < NNZ / 4; t += nt) {
        float4 p4 = reinterpret_cast<const float4*>(probs)[t];
        float pv[4] = {p4.x, p4.y, p4.z, p4.w};
#pragma unroll
        for (int j = 0; j < 4; j++) {
            unsigned bits = __float_as_uint(pv[j]);
            int idx = 4 * t + j;
            if (bits == s.T && (idx >> 11) == ib) atomicAdd(&sA[idx & 2047], 1u);
        }
    }
    __syncthreads();
    for (int i = threadIdx.x; i < 2048; i += NTH) {
        unsigned v = sA[i];
        if (v) atomicAdd(&g_h4[i], v);
    }
}

// ---------------- k_mask: local picks -> T, cutoff; mask + edge soft sums ----------------
__global__ void k_mask(const int* __restrict__ E, const float* __restrict__ probs,
                       float* __restrict__ soft, float* __restrict__ hard) {
    __shared__ unsigned sA[2048], sB[2048];
    __shared__ int s_ri, s_rr, s_rn;
    Sel2 s = picks012(sA, sB, &s_ri, &s_rr, &s_rn);
    unsigned T = s.T;
    int cut;
    if (s.skip) {
        cut = 0x7fffffff;
    } else {
        do_pick(g_h3, 1024, s.rank3, false, sA, sB, &s_ri, &s_rr, &s_rn);
        int ib = s_ri;  int rank4 = s_rr;
        do_pick(g_h4, 2048, rank4, false, sA, sB, &s_ri, &s_rr, &s_rn);
        cut = (ib << 11) | s_ri;
    }
    int t = blockIdx.x * blockDim.x + threadIdx.x;
    if (t >= NNZ / 8) return;
#pragma unroll
    for (int half = 0; half < 2; half++) {
        int idx = t * 2 + half;
        float4 p4 = reinterpret_cast<const float4*>(probs)[idx];
        int4   e4 = reinterpret_cast<const int4*>(E)[idx];
        int base = idx * 4;
        float pv[4] = {p4.x, p4.y, p4.z, p4.w};
        int   ev[4] = {e4.x, e4.y, e4.z, e4.w};
        float sf[4], hf[4];
#pragma unroll
        for (int j = 0; j < 4; j++) {
            unsigned bits = __float_as_uint(pv[j]);
            bool h = (bits > T) || (bits == T && (base + j) <= cut);
            hf[j] = h ? 1.0f : 0.0f;
            sf[j] = h ? ((1.0f - pv[j]) + pv[j]) : 0.0f;
            if (h)
                asm volatile("red.global.add.f32 [%0], %1;"
                             :: "l"(&g_sum_s[ev[j]]), "f"(sf[j]) : "memory");
        }
        reinterpret_cast<float4*>(soft)[idx] = make_float4(sf[0], sf[1], sf[2], sf[3]);
        reinterpret_cast<float4*>(hard)[idx] = make_float4(hf[0], hf[1], hf[2], hf[3]);
    }
}

// ---------------- k_edges ----------------
__global__ void k_edges(float* __restrict__ ep, float* __restrict__ es, float* __restrict__ eh) {
    int t = blockIdx.x * blockDim.x + threadIdx.x;
    if (t >= N_EDGES / 4) return;
    int4   c4 = reinterpret_cast<const int4*>(g_cnt)[t];
    float4 sp = reinterpret_cast<const float4*>(g_sum_p)[t];
    float4 ss = reinterpret_cast<const float4*>(g_sum_s)[t];
    float c0 = (float)(c4.x > 1 ? c4.x : 1);
    float c1 = (float)(c4.y > 1 ? c4.y : 1);
    float c2 = (float)(c4.z > 1 ? c4.z : 1);
    float c3 = (float)(c4.w > 1 ? c4.w : 1);
    reinterpret_cast<float4*>(ep)[t] = make_float4(sp.x / c0, sp.y / c1, sp.z / c2, sp.w / c3);
    reinterpret_cast<float4*>(es)[t] = make_float4(ss.x / c0, ss.y / c1, ss.z / c2, ss.w / c3);
    reinterpret_cast<float4*>(eh)[t] = make_float4(ss.x > 0.f ? 1.f : 0.f, ss.y > 0.f ? 1.f : 0.f,
                                                   ss.z > 0.f ? 1.f : 0.f, ss.w > 0.f ? 1.f : 0.f);
}

// ---------------- launcher ----------------
extern "C" void kernel_launch(void* const* d_in, const int* in_sizes, int n_in,
                              void* d_out, int out_size) {
    const float* x  = (const float*)d_in[0];
    const int*   V  = (const int*)d_in[1];
    const int*   E  = (const int*)d_in[2];
    const float* W1 = (const float*)d_in[3];
    const float* b1 = (const float*)d_in[4];
    const float* W2 = (const float*)d_in[5];
    const float* b2 = (const float*)d_in[6];

    float* out   = (float*)d_out;
    float* probs = out;
    float* soft  = out + NNZ;
    float* hard  = out + 2 * NNZ;
    float* ep    = out + 3 * NNZ;
    float* es    = ep + N_EDGES;
    float* eh    = es + N_EDGES;

    k_pre<<<256, 256>>>();                                                   // 1
    k_init<<<PROJ_BLKS + ZERO_BLKS + CNT_BLKS, 256>>>(x, W1, b1, E);         // 2
    k_scatter<<<(NNZ * 8 + 255) / 256, 256>>>(V, E);                         // 3
    k_logits<<<(NNZ * 4) / 256, 256>>>(V, E, W2, b2, probs);                 // 4 <- profiled
    k_h1<<<512, 256>>>(probs);                                               // 5
    k_h2<<<512, 256>>>(probs);                                               // 6
    k_h3<<<512, 256>>>(probs);                                               // 7 (fast exit)
    k_h4<<<512, 256>>>(probs);                                               // 8 (fast exit)
    k_mask<<<(NNZ / 8 + 255) / 256, 256>>>(E, probs, soft, hard);            // 9
    k_edges<<<(N_EDGES / 4 + 255) / 256, 256>>>(ep, es, eh);                 // 10
}

// round 12
// speedup vs baseline: 1.7488x; 1.7488x over previous
#include <cuda_runtime.h>
#include <cstdint>
#include <math.h>

#define N_NODES   100000
#define N_EDGES   200000
#define NNZ       2000000
#define HID       32
#define K_KEEP    1000000
#define NTH       256

// ---------------- device scratch (no allocations allowed) ----------------
__device__ __align__(16) float g_xa[N_NODES * HID];
__device__ __align__(16) float g_xb[N_NODES * HID];
__device__ __align__(16) float g_eb[N_EDGES * HID];
__device__ int      g_cnt[N_EDGES];
__device__ float    g_sum_p[N_EDGES];
__device__ float    g_sum_s[N_EDGES];
__device__ unsigned g_hist0[2048];
__device__ unsigned g_hist1[2048];
__device__ unsigned g_h2[1024];
__device__ unsigned g_h3[1024];
__device__ unsigned g_h4[2048];

// ---------------- shared-mem scan + threshold-bucket pick ----------------
__device__ void pick_bucket(unsigned* sA, unsigned* sB, int n, int rank, bool desc,
                            int* ri, int* rr, int* rn) {
    unsigned *in = sA, *out = sB;
    for (int off = 1; off < n; off <<= 1) {
        for (int i = threadIdx.x; i < n; i += NTH) {
            unsigned add = desc ? ((i + off < n) ? in[i + off] : 0u)
                                : ((i >= off) ? in[i - off] : 0u);
            out[i] = in[i] + add;
        }
        __syncthreads();
        unsigned* t = in; in = out; out = t;
    }
    for (int i = threadIdx.x; i < n; i += NTH) {
        unsigned adj = desc ? ((i + 1 < n) ? in[i + 1] : 0u)
                            : ((i > 0) ? in[i - 1] : 0u);
        if ((int)in[i] >= rank && (int)adj < rank) {
            *ri = i; *rr = rank - (int)adj; *rn = (int)(in[i] - adj);
        }
    }
    __syncthreads();
}

__device__ __forceinline__ void do_pick(const unsigned* gh, int n, int rank, bool desc,
                                        unsigned* sA, unsigned* sB,
                                        int* ri, int* rr, int* rn) {
    for (int i = threadIdx.x; i < n; i += NTH) sA[i] = gh[i];
    __syncthreads();
    pick_bucket(sA, sB, n, rank, desc, ri, rr, rn);
}

// ---------------- k_pre: zero all small state ----------------
__global__ void k_pre() {
    int tid = blockIdx.x * blockDim.x + threadIdx.x;
    int nt  = gridDim.x * blockDim.x;
    for (int i = tid; i < N_EDGES; i += nt) {
        g_cnt[i] = 0; g_sum_p[i] = 0.0f; g_sum_s[i] = 0.0f;
    }
    for (int i = tid; i < 2048; i += nt) { g_hist0[i] = 0u; g_hist1[i] = 0u; g_h4[i] = 0u; }
    for (int i = tid; i < 1024; i += nt) { g_h2[i] = 0u; g_h3[i] = 0u; }
}

// ---------------- k_init: proj (0..511) | zero eb (512..639) | count E (640..767) ----------------
#define PROJ_BLKS 512
#define ZERO_BLKS 128
#define CNT_BLKS  128
__global__ void k_init(const float* __restrict__ x,
                       const float* __restrict__ W1,
                       const float* __restrict__ b1,
                       const int* __restrict__ E) {
    int b = blockIdx.x;
    if (b < PROJ_BLKS) {
        __shared__ float sW[128 * 32];
        for (int i = threadIdx.x; i < 128 * 32; i += blockDim.x) sW[i] = W1[i];
        __syncthreads();
        int lane = threadIdx.x & 31;
        int warp = threadIdx.x >> 5;
        float bb = b1[lane];
        for (int row = b * 8 + warp; row < N_NODES; row += PROJ_BLKS * 8) {
            float x0 = x[row * 64 + lane];
            float x1 = x[row * 64 + 32 + lane];
            float aa = bb, ab = 0.0f;
#pragma unroll
            for (int k = 0; k < 32; k++) {
                float xv = __shfl_sync(0xffffffffu, x0, k);
                aa += xv * sW[k * 32 + lane];
                ab += xv * sW[(64 + k) * 32 + lane];
            }
#pragma unroll
            for (int k = 0; k < 32; k++) {
                float xv = __shfl_sync(0xffffffffu, x1, k);
                aa += xv * sW[(32 + k) * 32 + lane];
                ab += xv * sW[(96 + k) * 32 + lane];
            }
            g_xa[row * 32 + lane] = aa;
            g_xb[row * 32 + lane] = ab;
        }
    } else if (b < PROJ_BLKS + ZERO_BLKS) {
        int tid = (b - PROJ_BLKS) * blockDim.x + threadIdx.x;
        int nt  = ZERO_BLKS * blockDim.x;
        float4 z4 = make_float4(0.f, 0.f, 0.f, 0.f);
        float4* eb4 = reinterpret_cast<float4*>(g_eb);
        for (int i = tid; i < N_EDGES * HID / 4; i += nt) eb4[i] = z4;
    } else {
        int tid = (b - PROJ_BLKS - ZERO_BLKS) * blockDim.x + threadIdx.x;
        int nt  = CNT_BLKS * blockDim.x;
        for (int t = tid; t < NNZ / 4; t += nt) {
            int4 e4 = reinterpret_cast<const int4*>(E)[t];
            atomicAdd(&g_cnt[e4.x], 1);
            atomicAdd(&g_cnt[e4.y], 1);
            atomicAdd(&g_cnt[e4.z], 1);
            atomicAdd(&g_cnt[e4.w], 1);
        }
    }
}

// ---------------- k_scatter: 8 lanes / nnz, one red.v4 each ----------------
__global__ void k_scatter(const int* __restrict__ V, const int* __restrict__ E) {
    int tid = blockIdx.x * blockDim.x + threadIdx.x;
    int g   = tid >> 3;
    int sub = tid & 7;
    if (g >= NNZ) return;
    int v = V[g], e = E[g];
    float4 val = *reinterpret_cast<const float4*>(&g_xb[v * 32 + sub * 4]);
    float* dst = &g_eb[e * 32 + sub * 4];
    asm volatile("red.global.add.v4.f32 [%0], {%1,%2,%3,%4};"
                 :: "l"(dst), "f"(val.x), "f"(val.y), "f"(val.z), "f"(val.w)
                 : "memory");
}

// ---------------- k_logits: 4 lanes / nnz (clean; measured 57us) ----------------
__global__ void k_logits(const int* __restrict__ V, const int* __restrict__ E,
                         const float* __restrict__ W2, const float* __restrict__ b2,
                         float* __restrict__ out_probs) {
    int tid = blockIdx.x * blockDim.x + threadIdx.x;
    int g   = tid >> 2;
    int sub = tid & 3;
    if (g >= NNZ) return;
    int v = V[g], e = E[g];
    int c = g_cnt[e];
    float ic = 1.0f / (float)(c > 1 ? c : 1);
    const float4* pa = reinterpret_cast<const float4*>(&g_xa[v * 32]) + sub * 2;
    const float4* pm = reinterpret_cast<const float4*>(&g_eb[e * 32]) + sub * 2;
    const float4* pw = reinterpret_cast<const float4*>(W2) + sub * 2;
    float4 a0 = pa[0], a1 = pa[1];
    float4 m0 = pm[0], m1 = pm[1];
    float4 w0 = pw[0], w1 = pw[1];
    float part =
        fmaxf(a0.x + m0.x * ic, 0.0f) * w0.x +
        fmaxf(a0.y + m0.y * ic, 0.0f) * w0.y +
        fmaxf(a0.z + m0.z * ic, 0.0f) * w0.z +
        fmaxf(a0.w + m0.w * ic, 0.0f) * w0.w +
        fmaxf(a1.x + m1.x * ic, 0.0f) * w1.x +
        fmaxf(a1.y + m1.y * ic, 0.0f) * w1.y +
        fmaxf(a1.z + m1.z * ic, 0.0f) * w1.z +
        fmaxf(a1.w + m1.w * ic, 0.0f) * w1.w;
    part += __shfl_xor_sync(0xffffffffu, part, 2);
    part += __shfl_xor_sync(0xffffffffu, part, 1);
    if (sub == 0) {
        float z = part + b2[0];
        float p = 1.0f / (1.0f + __expf(-z));
        out_probs[g] = p;
        asm volatile("red.global.add.f32 [%0], %1;" :: "l"(&g_sum_p[e]), "f"(p) : "memory");
    }
}

// ---------------- k_hist0: shared-bin phase-0 histogram (measured ~6us) ----------------
__global__ void k_hist0(const float* __restrict__ probs) {
    __shared__ unsigned sh[2048];
    for (int i = threadIdx.x; i < 2048; i += blockDim.x) sh[i] = 0u;
    __syncthreads();
    int tid = blockIdx.x * blockDim.x + threadIdx.x;
    int nt  = gridDim.x * blockDim.x;
    for (int t = tid; t < NNZ / 4; t += nt) {
        float4 p4 = reinterpret_cast<const float4*>(probs)[t];
        atomicAdd(&sh[__float_as_uint(p4.x) >> 21], 1u);
        atomicAdd(&sh[__float_as_uint(p4.y) >> 21], 1u);
        atomicAdd(&sh[__float_as_uint(p4.z) >> 21], 1u);
        atomicAdd(&sh[__float_as_uint(p4.w) >> 21], 1u);
    }
    __syncthreads();
    for (int i = threadIdx.x; i < 2048; i += blockDim.x) {
        unsigned vv = sh[i];
        if (vv) atomicAdd(&g_hist0[i], vv);
    }
}

// ---------------- k_h1: pick0 -> p1; filtered hist1 pass ----------------
__global__ void k_h1(const float* __restrict__ probs) {
    __shared__ unsigned sA[2048], sB[2048];
    __shared__ int s_ri, s_rr, s_rn;
    do_pick(g_hist0, 2048, K_KEEP, true, sA, sB, &s_ri, &s_rr, &s_rn);
    unsigned p1 = (unsigned)s_ri;
    for (int i = threadIdx.x; i < 2048; i += NTH) sA[i] = 0u;
    __syncthreads();
    int tid = blockIdx.x * blockDim.x + threadIdx.x;
    int nt  = gridDim.x * blockDim.x;
    for (int t = tid; t < NNZ / 4; t += nt) {
        float4 p4 = reinterpret_cast<const float4*>(probs)[t];
        float pv[4] = {p4.x, p4.y, p4.z, p4.w};
#pragma unroll
        for (int j = 0; j < 4; j++) {
            unsigned bits = __float_as_uint(pv[j]);
            if ((bits >> 21) == p1) atomicAdd(&sA[(bits >> 10) & 2047u], 1u);
        }
    }
    __syncthreads();
    for (int i = threadIdx.x; i < 2048; i += NTH) {
        unsigned v = sA[i];
        if (v) atomicAdd(&g_hist1[i], v);
    }
}

// ---------------- k_h2: picks0-1 -> p2; filtered h2 pass ----------------
__global__ void k_h2(const float* __restrict__ probs) {
    __shared__ unsigned sA[2048], sB[2048];
    __shared__ int s_ri, s_rr, s_rn;
    do_pick(g_hist0, 2048, K_KEEP, true, sA, sB, &s_ri, &s_rr, &s_rn);
    unsigned p1 = (unsigned)s_ri;  int rank1 = s_rr;
    do_pick(g_hist1, 2048, rank1, true, sA, sB, &s_ri, &s_rr, &s_rn);
    unsigned p2 = (p1 << 11) | (unsigned)s_ri;
    for (int i = threadIdx.x; i < 1024; i += NTH) sA[i] = 0u;
    __syncthreads();
    int tid = blockIdx.x * blockDim.x + threadIdx.x;
    int nt  = gridDim.x * blockDim.x;
    for (int t = tid; t < NNZ / 4; t += nt) {
        float4 p4 = reinterpret_cast<const float4*>(probs)[t];
        float pv[4] = {p4.x, p4.y, p4.z, p4.w};
#pragma unroll
        for (int j = 0; j < 4; j++) {
            unsigned bits = __float_as_uint(pv[j]);
            if ((bits >> 10) == p2) atomicAdd(&sA[bits & 1023u], 1u);
        }
    }
    __syncthreads();
    for (int i = threadIdx.x; i < 1024; i += NTH) {
        unsigned v = sA[i];
        if (v) atomicAdd(&g_h2[i], v);
    }
}

// prologue shared by h3/h4/mask: picks 0..2
struct Sel2 { unsigned T; int skip; int rank3; };
__device__ __forceinline__ Sel2 picks012(unsigned* sA, unsigned* sB,
                                         int* ri, int* rr, int* rn) {
    do_pick(g_hist0, 2048, K_KEEP, true, sA, sB, ri, rr, rn);
    unsigned p1 = (unsigned)*ri;  int rank1 = *rr;
    do_pick(g_hist1, 2048, rank1, true, sA, sB, ri, rr, rn);
    unsigned p2 = (p1 << 11) | (unsigned)*ri;  int rank2 = *rr;
    do_pick(g_h2, 1024, rank2, true, sA, sB, ri, rr, rn);
    Sel2 s;
    s.T = (p2 << 10) | (unsigned)*ri;
    s.rank3 = *rr;
    s.skip = (*rr >= *rn) ? 1 : 0;
    return s;
}

// ---------------- k_h3: ties' index-high histogram (rare path) ----------------
__global__ void k_h3(const float* __restrict__ probs) {
    __shared__ unsigned sA[2048], sB[2048];
    __shared__ int s_ri, s_rr, s_rn;
    Sel2 s = picks012(sA, sB, &s_ri, &s_rr, &s_rn);
    if (s.skip) return;
    for (int i = threadIdx.x; i < 1024; i += NTH) sA[i] = 0u;
    __syncthreads();
    int tid = blockIdx.x * blockDim.x + threadIdx.x;
    int nt  = gridDim.x * blockDim.x;
    for (int t = tid; t < NNZ / 4; t += nt) {
        float4 p4 = reinterpret_cast<const float4*>(probs)[t];
        float pv[4] = {p4.x, p4.y, p4.z, p4.w};
#pragma unroll
        for (int j = 0; j < 4; j++) {
            unsigned bits = __float_as_uint(pv[j]);
            if (bits == s.T) atomicAdd(&sA[(unsigned)(4 * t + j) >> 11], 1u);
        }
    }
    __syncthreads();
    for (int i = threadIdx.x; i < 1024; i += NTH) {
        unsigned v = sA[i];
        if (v) atomicAdd(&g_h3[i], v);
    }
}

// ---------------- k_h4: ties' index-low histogram (rare path) ----------------
__global__ void k_h4(const float* __restrict__ probs) {
    __shared__ unsigned sA[2048], sB[2048];
    __shared__ int s_ri, s_rr, s_rn;
    Sel2 s = picks012(sA, sB, &s_ri, &s_rr, &s_rn);
    if (s.skip) return;
    do_pick(g_h3, 1024, s.rank3, false, sA, sB, &s_ri, &s_rr, &s_rn);
    int ib = s_ri;
    for (int i = threadIdx.x; i < 2048; i += NTH) sA[i] = 0u;
    __syncthreads();
    int tid = blockIdx.x * blockDim.x + threadIdx.x;
    int nt  = gridDim.x * blockDim.x;
    for (int t = tid; t < NNZ / 4; t += nt) {
        float4 p4 = reinterpret_cast<const float4*>(probs)[t];
        float pv[4] = {p4.x, p4.y, p4.z, p4.w};
#pragma unroll
        for (int j = 0; j < 4; j++) {
            unsigned bits = __float_as_uint(pv[j]);
            int idx = 4 * t + j;
            if (bits == s.T && (idx >> 11) == ib) atomicAdd(&sA[idx & 2047], 1u);
        }
    }
    __syncthreads();
    for (int i = threadIdx.x; i < 2048; i += NTH) {
        unsigned v = sA[i];
        if (v) atomicAdd(&g_h4[i], v);
    }
}

// ---------------- k_mask: local picks -> T, cutoff; mask + edge soft sums ----------------
__global__ void k_mask(const int* __restrict__ E, const float* __restrict__ probs,
                       float* __restrict__ soft, float* __restrict__ hard) {
    __shared__ unsigned sA[2048], sB[2048];
    __shared__ int s_ri, s_rr, s_rn;
    Sel2 s = picks012(sA, sB, &s_ri, &s_rr, &s_rn);
    unsigned T = s.T;
    int cut;
    if (s.skip) {
        cut = 0x7fffffff;
    } else {
        do_pick(g_h3, 1024, s.rank3, false, sA, sB, &s_ri, &s_rr, &s_rn);
        int ib = s_ri;  int rank4 = s_rr;
        do_pick(g_h4, 2048, rank4, false, sA, sB, &s_ri, &s_rr, &s_rn);
        cut = (ib << 11) | s_ri;
    }
    int t = blockIdx.x * blockDim.x + threadIdx.x;
    if (t >= NNZ / 8) return;
#pragma unroll
    for (int half = 0; half < 2; half++) {
        int idx = t * 2 + half;
        float4 p4 = reinterpret_cast<const float4*>(probs)[idx];
        int4   e4 = reinterpret_cast<const int4*>(E)[idx];
        int base = idx * 4;
        float pv[4] = {p4.x, p4.y, p4.z, p4.w};
        int   ev[4] = {e4.x, e4.y, e4.z, e4.w};
        float sf[4], hf[4];
#pragma unroll
        for (int j = 0; j < 4; j++) {
            unsigned bits = __float_as_uint(pv[j]);
            bool h = (bits > T) || (bits == T && (base + j) <= cut);
            hf[j] = h ? 1.0f : 0.0f;
            sf[j] = h ? ((1.0f - pv[j]) + pv[j]) : 0.0f;
            if (h)
                asm volatile("red.global.add.f32 [%0], %1;"
                             :: "l"(&g_sum_s[ev[j]]), "f"(sf[j]) : "memory");
        }
        reinterpret_cast<float4*>(soft)[idx] = make_float4(sf[0], sf[1], sf[2], sf[3]);
        reinterpret_cast<float4*>(hard)[idx] = make_float4(hf[0], hf[1], hf[2], hf[3]);
    }
}

// ---------------- k_edges ----------------
__global__ void k_edges(float* __restrict__ ep, float* __restrict__ es, float* __restrict__ eh) {
    int t = blockIdx.x * blockDim.x + threadIdx.x;
    if (t >= N_EDGES / 4) return;
    int4   c4 = reinterpret_cast<const int4*>(g_cnt)[t];
    float4 sp = reinterpret_cast<const float4*>(g_sum_p)[t];
    float4 ss = reinterpret_cast<const float4*>(g_sum_s)[t];
    float c0 = (float)(c4.x > 1 ? c4.x : 1);
    float c1 = (float)(c4.y > 1 ? c4.y : 1);
    float c2 = (float)(c4.z > 1 ? c4.z : 1);
    float c3 = (float)(c4.w > 1 ? c4.w : 1);
    reinterpret_cast<float4*>(ep)[t] = make_float4(sp.x / c0, sp.y / c1, sp.z / c2, sp.w / c3);
    reinterpret_cast<float4*>(es)[t] = make_float4(ss.x / c0, ss.y / c1, ss.z / c2, ss.w / c3);
    reinterpret_cast<float4*>(eh)[t] = make_float4(ss.x > 0.f ? 1.f : 0.f, ss.y > 0.f ? 1.f : 0.f,
                                                   ss.z > 0.f ? 1.f : 0.f, ss.w > 0.f ? 1.f : 0.f);
}

// ---------------- launcher ----------------
extern "C" void kernel_launch(void* const* d_in, const int* in_sizes, int n_in,
                              void* d_out, int out_size) {
    const float* x  = (const float*)d_in[0];
    const int*   V  = (const int*)d_in[1];
    const int*   E  = (const int*)d_in[2];
    const float* W1 = (const float*)d_in[3];
    const float* b1 = (const float*)d_in[4];
    const float* W2 = (const float*)d_in[5];
    const float* b2 = (const float*)d_in[6];

    float* out   = (float*)d_out;
    float* probs = out;
    float* soft  = out + NNZ;
    float* hard  = out + 2 * NNZ;
    float* ep    = out + 3 * NNZ;
    float* es    = ep + N_EDGES;
    float* eh    = es + N_EDGES;

    k_pre<<<256, 256>>>();                                                   // 1
    k_init<<<PROJ_BLKS + ZERO_BLKS + CNT_BLKS, 256>>>(x, W1, b1, E);         // 2
    k_scatter<<<(NNZ * 8 + 255) / 256, 256>>>(V, E);                         // 3
    k_logits<<<(NNZ * 4 + 255) / 256, 256>>>(V, E, W2, b2, probs);           // 4 <- profiled
    k_hist0<<<512, 256>>>(probs);                                            // 5
    k_h1<<<512, 256>>>(probs);                                               // 6
    k_h2<<<512, 256>>>(probs);                                               // 7
    k_h3<<<512, 256>>>(probs);                                               // 8 (fast exit)
    k_h4<<<512, 256>>>(probs);                                               // 9 (fast exit)
    k_mask<<<(NNZ / 8 + 255) / 256, 256>>>(E, probs, soft, hard);            // 10
    k_edges<<<(N_EDGES / 4 + 255) / 256, 256>>>(ep, es, eh);                 // 11
}

// round 13
// speedup vs baseline: 2.2514x; 1.2874x over previous
#include <cuda_runtime.h>
#include <cstdint>
#include <math.h>

#define N_NODES   100000
#define N_EDGES   200000
#define NNZ       2000000
#define DIM       64
#define HID       32
#define K_KEEP    1000000

// ---------------- device scratch (no allocations allowed) ----------------
struct Ctrl {
    unsigned p1, p2, Tbits;
    int rank;
    int skip;
    int ib;
    int cutoff;
};

__device__ __align__(16) float g_xa[N_NODES * HID];   // x @ W1[:64] + b1
__device__ __align__(16) float g_xb[N_NODES * HID];   // x @ W1[64:]
__device__ __align__(16) float g_eb[N_EDGES * HID];   // segment sums of xb
__device__ int      g_cnt[N_EDGES];
__device__ float    g_sum_p[N_EDGES];
__device__ float    g_sum_s[N_EDGES];
__device__ unsigned g_hist[5][2048];
__device__ Ctrl     g_ctrl;

// ---------------- zero scratch ----------------
__global__ void k_zero() {
    int tid = blockIdx.x * blockDim.x + threadIdx.x;
    int nt  = gridDim.x * blockDim.x;
    for (int i = tid; i < N_EDGES * HID; i += nt) g_eb[i] = 0.0f;
    for (int i = tid; i < N_EDGES; i += nt) {
        g_cnt[i] = 0; g_sum_p[i] = 0.0f; g_sum_s[i] = 0.0f;
    }
    for (int i = tid; i < 5 * 2048; i += nt) ((unsigned*)g_hist)[i] = 0u;
    if (tid == 0) {
        g_ctrl.p1 = 0; g_ctrl.p2 = 0; g_ctrl.Tbits = 0;
        g_ctrl.rank = 0; g_ctrl.skip = 0; g_ctrl.ib = 0; g_ctrl.cutoff = 0;
    }
}

// ---------------- per-node projections: xa = x@W1a + b1, xb = x@W1b ----------------
__global__ void k_proj(const float* __restrict__ x,
                       const float* __restrict__ W1,
                       const float* __restrict__ b1) {
    __shared__ float sW[128 * 32];
    for (int i = threadIdx.x; i < 128 * 32; i += blockDim.x) sW[i] = W1[i];
    __syncthreads();
    int lane = threadIdx.x & 31;
    int warp = threadIdx.x >> 5;
    int wpb  = blockDim.x >> 5;
    float bb = b1[lane];
    for (int row = blockIdx.x * wpb + warp; row < N_NODES; row += gridDim.x * wpb) {
        float x0 = x[row * 64 + lane];
        float x1 = x[row * 64 + 32 + lane];
        float aa = bb, ab = 0.0f;
#pragma unroll
        for (int k = 0; k < 32; k++) {
            float xv = __shfl_sync(0xffffffffu, x0, k);
            aa += xv * sW[k * 32 + lane];
            ab += xv * sW[(64 + k) * 32 + lane];
        }
#pragma unroll
        for (int k = 0; k < 32; k++) {
            float xv = __shfl_sync(0xffffffffu, x1, k);
            aa += xv * sW[(32 + k) * 32 + lane];
            ab += xv * sW[(96 + k) * 32 + lane];
        }
        g_xa[row * 32 + lane] = aa;
        g_xb[row * 32 + lane] = ab;
    }
}

// ---------------- scatter xb into per-edge sums (v4 reductions) ----------------
__global__ void k_scatter(const int* __restrict__ V, const int* __restrict__ E) {
    int tid = blockIdx.x * blockDim.x + threadIdx.x;
    int g   = tid >> 3;
    int sub = tid & 7;
    if (g >= NNZ) return;
    int v = V[g], e = E[g];
    float4 val = *reinterpret_cast<const float4*>(&g_xb[v * 32 + sub * 4]);
    float* dst = &g_eb[e * 32 + sub * 4];
    asm volatile("red.global.add.v4.f32 [%0], {%1,%2,%3,%4};"
                 :: "l"(dst), "f"(val.x), "f"(val.y), "f"(val.z), "f"(val.w)
                 : "memory");
    if (sub == 0) atomicAdd(&g_cnt[e], 1);
}

// ---------------- fused MLP: probs + edge prob sums (4 lanes / nnz; measured 57us) ----------------
__global__ void k_logits(const int* __restrict__ V, const int* __restrict__ E,
                         const float* __restrict__ W2, const float* __restrict__ b2,
                         float* __restrict__ out_probs) {
    int tid = blockIdx.x * blockDim.x + threadIdx.x;
    int g   = tid >> 2;
    int sub = tid & 3;
    if (g >= NNZ) return;
    int v = V[g], e = E[g];
    int c = g_cnt[e];
    float ic = 1.0f / (float)(c > 1 ? c : 1);
    const float4* pa = reinterpret_cast<const float4*>(&g_xa[v * 32]) + sub * 2;
    const float4* pm = reinterpret_cast<const float4*>(&g_eb[e * 32]) + sub * 2;
    const float4* pw = reinterpret_cast<const float4*>(W2) + sub * 2;
    float4 a0 = pa[0], a1 = pa[1];
    float4 m0 = pm[0], m1 = pm[1];
    float4 w0 = pw[0], w1 = pw[1];
    float part =
        fmaxf(a0.x + m0.x * ic, 0.0f) * w0.x +
        fmaxf(a0.y + m0.y * ic, 0.0f) * w0.y +
        fmaxf(a0.z + m0.z * ic, 0.0f) * w0.z +
        fmaxf(a0.w + m0.w * ic, 0.0f) * w0.w +
        fmaxf(a1.x + m1.x * ic, 0.0f) * w1.x +
        fmaxf(a1.y + m1.y * ic, 0.0f) * w1.y +
        fmaxf(a1.z + m1.z * ic, 0.0f) * w1.z +
        fmaxf(a1.w + m1.w * ic, 0.0f) * w1.w;
    part += __shfl_xor_sync(0xffffffffu, part, 2);
    part += __shfl_xor_sync(0xffffffffu, part, 1);
    if (sub == 0) {
        float z = part + b2[0];
        float p = 1.0f / (1.0f + __expf(-z));
        out_probs[g] = p;
        asm volatile("red.global.add.f32 [%0], %1;" :: "l"(&g_sum_p[e]), "f"(p) : "memory");
    }
}

// ---------------- selection: histograms (R1 verbatim) ----------------
__global__ void k_hist(const float* __restrict__ probs, int phase) {
    __shared__ unsigned sh[2048];
    for (int i = threadIdx.x; i < 2048; i += blockDim.x) sh[i] = 0u;
    __syncthreads();
    unsigned p1 = g_ctrl.p1, p2 = g_ctrl.p2, Tb = g_ctrl.Tbits;
    int ib = g_ctrl.ib, skip = g_ctrl.skip;
    if (phase >= 3 && skip) return;   // uniform across all threads
    int tid = blockIdx.x * blockDim.x + threadIdx.x;
    int nt  = gridDim.x * blockDim.x;
    for (int i = tid; i < NNZ; i += nt) {
        unsigned bits = __float_as_uint(probs[i]);
        int b = -1;
        if (phase == 0)      b = (int)(bits >> 21);
        else if (phase == 1) { if ((bits >> 21) == p1) b = (int)((bits >> 10) & 2047u); }
        else if (phase == 2) { if ((bits >> 10) == p2) b = (int)(bits & 1023u); }
        else if (phase == 3) { if (bits == Tb) b = i >> 11; }
        else                 { if (bits == Tb && (i >> 11) == ib) b = i & 2047; }
        if (b >= 0) atomicAdd(&sh[b], 1u);
    }
    __syncthreads();
    for (int i = threadIdx.x; i < 2048; i += blockDim.x) {
        unsigned vv = sh[i];
        if (vv) atomicAdd(&g_hist[phase][i], vv);
    }
}

// ---------------- selection: scan + pick bucket (R1 verbatim) ----------------
__global__ void k_scan(int phase) {
    __shared__ unsigned sA[2048], sB[2048];
    if (phase >= 3 && g_ctrl.skip) return;
    int n   = (phase == 2 || phase == 3) ? 1024 : 2048;
    int tid = threadIdx.x;  // blockDim = 1024
    const unsigned* hist = g_hist[phase];
    for (int i = tid; i < n; i += 1024) sA[i] = hist[i];
    __syncthreads();
    bool desc = (phase <= 2);
    unsigned *in = sA, *out = sB;
    for (int off = 1; off < n; off <<= 1) {
        for (int i = tid; i < n; i += 1024) {
            unsigned add = 0;
            if (desc) { if (i + off < n) add = in[i + off]; }
            else      { if (i >= off)    add = in[i - off]; }
            out[i] = in[i] + add;
        }
        __syncthreads();
        unsigned* t = in; in = out; out = t;
    }
    int rank = (phase == 0) ? K_KEEP : g_ctrl.rank;
    for (int i = tid; i < n; i += 1024) {
        bool hit;
        unsigned adj;
        if (desc) {
            unsigned nxt = (i + 1 < n) ? in[i + 1] : 0u;
            hit = ((int)in[i] >= rank) && ((int)nxt < rank);
            adj = nxt;
        } else {
            unsigned prv = (i > 0) ? in[i - 1] : 0u;
            hit = ((int)in[i] >= rank) && ((int)prv < rank);
            adj = prv;
        }
        if (hit) {
            if (phase == 0)      { g_ctrl.p1 = (unsigned)i; g_ctrl.rank = rank - (int)adj; }
            else if (phase == 1) { g_ctrl.p2 = (g_ctrl.p1 << 11) | (unsigned)i; g_ctrl.rank = rank - (int)adj; }
            else if (phase == 2) {
                g_ctrl.Tbits = (g_ctrl.p2 << 10) | (unsigned)i;
                int r   = rank - (int)adj;
                int neq = (int)(in[i] - adj);
                if (r >= neq) { g_ctrl.skip = 1; g_ctrl.cutoff = 0x7fffffff; }
                else          { g_ctrl.skip = 0; g_ctrl.rank = r; }
            }
            else if (phase == 3) { g_ctrl.ib = i; g_ctrl.rank = rank - (int)adj; }
            else                 { g_ctrl.cutoff = (g_ctrl.ib << 11) | i; }
        }
    }
}

// ---------------- hard/soft mask + edge soft sums (R1 + guarded red) ----------------
__global__ void k_mask(const int* __restrict__ E, const float* __restrict__ probs,
                       float* __restrict__ soft, float* __restrict__ hard) {
    int i = blockIdx.x * blockDim.x + threadIdx.x;
    if (i >= NNZ) return;
    float p = probs[i];
    unsigned bits = __float_as_uint(p);
    unsigned T = g_ctrl.Tbits;
    bool h = (bits > T) || (bits == T && i <= g_ctrl.cutoff);
    float hf = h ? 1.0f : 0.0f;
    float sf = h ? ((1.0f - p) + p) : 0.0f;   // straight-through forward value
    soft[i] = sf;
    hard[i] = hf;
    if (h)
        asm volatile("red.global.add.f32 [%0], %1;" :: "l"(&g_sum_s[E[i]]), "f"(sf) : "memory");
}

// ---------------- edge outputs (R1 verbatim) ----------------
__global__ void k_edges(float* __restrict__ ep, float* __restrict__ es, float* __restrict__ eh) {
    int e = blockIdx.x * blockDim.x + threadIdx.x;
    if (e >= N_EDGES) return;
    int ci = g_cnt[e];
    float c = (float)(ci > 1 ? ci : 1);
    float ss = g_sum_s[e];
    ep[e] = g_sum_p[e] / c;
    es[e] = ss / c;
    eh[e] = (ss > 0.0f) ? 1.0f : 0.0f;
}

// ---------------- launcher ----------------
extern "C" void kernel_launch(void* const* d_in, const int* in_sizes, int n_in,
                              void* d_out, int out_size) {
    const float* x  = (const float*)d_in[0];
    const int*   V  = (const int*)d_in[1];
    const int*   E  = (const int*)d_in[2];
    const float* W1 = (const float*)d_in[3];
    const float* b1 = (const float*)d_in[4];
    const float* W2 = (const float*)d_in[5];
    const float* b2 = (const float*)d_in[6];

    float* out   = (float*)d_out;
    float* probs = out;
    float* soft  = out + NNZ;
    float* hard  = out + 2 * NNZ;
    float* ep    = out + 3 * NNZ;
    float* es    = ep + N_EDGES;
    float* eh    = es + N_EDGES;

    k_zero<<<512, 256>>>();                                          // 1
    k_proj<<<512, 256>>>(x, W1, b1);                                 // 2
    k_scatter<<<(NNZ * 8 + 255) / 256, 256>>>(V, E);                 // 3
    k_logits<<<(NNZ * 4 + 255) / 256, 256>>>(V, E, W2, b2, probs);   // 4 <- profiled
    for (int ph = 0; ph < 5; ph++) {
        k_hist<<<512, 256>>>(probs, ph);
        k_scan<<<1, 1024>>>(ph);
    }
    k_mask<<<(NNZ + 255) / 256, 256>>>(E, probs, soft, hard);
    k_edges<<<(N_EDGES + 255) / 256, 256>>>(ep, es, eh);
}

// round 14
// speedup vs baseline: 2.3527x; 1.0450x over previous
#include <cuda_runtime.h>
#include <cstdint>
#include <math.h>

#define N_NODES   100000
#define N_EDGES   200000
#define NNZ       2000000
#define DIM       64
#define HID       32
#define K_KEEP    1000000

// ---------------- device scratch (no allocations allowed) ----------------
struct Ctrl {
    unsigned p1, p2, Tbits;
    int rank;
    int skip;
    int ib;
    int cutoff;
};

__device__ __align__(16) float g_xa[N_NODES * HID];   // x @ W1[:64] + b1
__device__ __align__(16) float g_xb[N_NODES * HID];   // x @ W1[64:]
__device__ __align__(16) float g_eb[N_EDGES * HID];   // segment sums of xb
__device__ int      g_cnt[N_EDGES];
__device__ float    g_sum_p[N_EDGES];
__device__ float    g_sum_s[N_EDGES];
__device__ unsigned g_hist[5][2048];
__device__ Ctrl     g_ctrl;

// ---------------- zero scratch (vectorized) ----------------
__global__ void k_zero() {
    int tid = blockIdx.x * blockDim.x + threadIdx.x;
    int nt  = gridDim.x * blockDim.x;
    float4 z4 = make_float4(0.f, 0.f, 0.f, 0.f);
    float4* eb4 = reinterpret_cast<float4*>(g_eb);
    for (int i = tid; i < N_EDGES * HID / 4; i += nt) eb4[i] = z4;
    for (int i = tid; i < N_EDGES; i += nt) {
        g_cnt[i] = 0; g_sum_p[i] = 0.0f; g_sum_s[i] = 0.0f;
    }
    for (int i = tid; i < 5 * 2048; i += nt) ((unsigned*)g_hist)[i] = 0u;
    if (tid == 0) {
        g_ctrl.p1 = 0; g_ctrl.p2 = 0; g_ctrl.Tbits = 0;
        g_ctrl.rank = 0; g_ctrl.skip = 0; g_ctrl.ib = 0; g_ctrl.cutoff = 0;
    }
}

// ---------------- per-node projections: xa = x@W1a + b1, xb = x@W1b ----------------
__global__ void k_proj(const float* __restrict__ x,
                       const float* __restrict__ W1,
                       const float* __restrict__ b1) {
    __shared__ float sW[128 * 32];
    for (int i = threadIdx.x; i < 128 * 32; i += blockDim.x) sW[i] = W1[i];
    __syncthreads();
    int lane = threadIdx.x & 31;
    int warp = threadIdx.x >> 5;
    int wpb  = blockDim.x >> 5;
    float bb = b1[lane];
    for (int row = blockIdx.x * wpb + warp; row < N_NODES; row += gridDim.x * wpb) {
        float x0 = x[row * 64 + lane];
        float x1 = x[row * 64 + 32 + lane];
        float aa = bb, ab = 0.0f;
#pragma unroll
        for (int k = 0; k < 32; k++) {
            float xv = __shfl_sync(0xffffffffu, x0, k);
            aa += xv * sW[k * 32 + lane];
            ab += xv * sW[(64 + k) * 32 + lane];
        }
#pragma unroll
        for (int k = 0; k < 32; k++) {
            float xv = __shfl_sync(0xffffffffu, x1, k);
            aa += xv * sW[(32 + k) * 32 + lane];
            ab += xv * sW[(96 + k) * 32 + lane];
        }
        g_xa[row * 32 + lane] = aa;
        g_xb[row * 32 + lane] = ab;
    }
}

// ---------------- scatter xb into per-edge sums (v4 reductions) ----------------
__global__ void k_scatter(const int* __restrict__ V, const int* __restrict__ E) {
    int tid = blockIdx.x * blockDim.x + threadIdx.x;
    int g   = tid >> 3;
    int sub = tid & 7;
    if (g >= NNZ) return;
    int v = V[g], e = E[g];
    float4 val = *reinterpret_cast<const float4*>(&g_xb[v * 32 + sub * 4]);
    float* dst = &g_eb[e * 32 + sub * 4];
    asm volatile("red.global.add.v4.f32 [%0], {%1,%2,%3,%4};"
                 :: "l"(dst), "f"(val.x), "f"(val.y), "f"(val.z), "f"(val.w)
                 : "memory");
    if (sub == 0) atomicAdd(&g_cnt[e], 1);
}

// ---------------- fused MLP: probs + edge prob sums (4 lanes / nnz) ----------------
__global__ void k_logits(const int* __restrict__ V, const int* __restrict__ E,
                         const float* __restrict__ W2, const float* __restrict__ b2,
                         float* __restrict__ out_probs) {
    int tid = blockIdx.x * blockDim.x + threadIdx.x;
    int g   = tid >> 2;
    int sub = tid & 3;
    if (g >= NNZ) return;
    int v = V[g], e = E[g];
    int c = g_cnt[e];
    float ic = 1.0f / (float)(c > 1 ? c : 1);
    const float4* pa = reinterpret_cast<const float4*>(&g_xa[v * 32]) + sub * 2;
    const float4* pm = reinterpret_cast<const float4*>(&g_eb[e * 32]) + sub * 2;
    const float4* pw = reinterpret_cast<const float4*>(W2) + sub * 2;
    float4 a0 = pa[0], a1 = pa[1];
    float4 m0 = pm[0], m1 = pm[1];
    float4 w0 = pw[0], w1 = pw[1];
    float part =
        fmaxf(a0.x + m0.x * ic, 0.0f) * w0.x +
        fmaxf(a0.y + m0.y * ic, 0.0f) * w0.y +
        fmaxf(a0.z + m0.z * ic, 0.0f) * w0.z +
        fmaxf(a0.w + m0.w * ic, 0.0f) * w0.w +
        fmaxf(a1.x + m1.x * ic, 0.0f) * w1.x +
        fmaxf(a1.y + m1.y * ic, 0.0f) * w1.y +
        fmaxf(a1.z + m1.z * ic, 0.0f) * w1.z +
        fmaxf(a1.w + m1.w * ic, 0.0f) * w1.w;
    part += __shfl_xor_sync(0xffffffffu, part, 2);
    part += __shfl_xor_sync(0xffffffffu, part, 1);
    if (sub == 0) {
        float z = part + b2[0];
        float p = 1.0f / (1.0f + __expf(-z));
        out_probs[g] = p;
        asm volatile("red.global.add.f32 [%0], %1;" :: "l"(&g_sum_p[e]), "f"(p) : "memory");
    }
}

// ---------------- selection: histograms (vectorized float4 loads) ----------------
__global__ void k_hist(const float* __restrict__ probs, int phase) {
    __shared__ unsigned sh[2048];
    for (int i = threadIdx.x; i < 2048; i += blockDim.x) sh[i] = 0u;
    __syncthreads();
    unsigned p1 = g_ctrl.p1, p2 = g_ctrl.p2, Tb = g_ctrl.Tbits;
    int ib = g_ctrl.ib, skip = g_ctrl.skip;
    if (phase >= 3 && skip) return;   // uniform across all threads
    int tid = blockIdx.x * blockDim.x + threadIdx.x;
    int nt  = gridDim.x * blockDim.x;
    for (int t = tid; t < NNZ / 4; t += nt) {
        float4 p4 = reinterpret_cast<const float4*>(probs)[t];
        float pv[4] = {p4.x, p4.y, p4.z, p4.w};
#pragma unroll
        for (int j = 0; j < 4; j++) {
            unsigned bits = __float_as_uint(pv[j]);
            int i = 4 * t + j;
            int b = -1;
            if (phase == 0)      b = (int)(bits >> 21);
            else if (phase == 1) { if ((bits >> 21) == p1) b = (int)((bits >> 10) & 2047u); }
            else if (phase == 2) { if ((bits >> 10) == p2) b = (int)(bits & 1023u); }
            else if (phase == 3) { if (bits == Tb) b = i >> 11; }
            else                 { if (bits == Tb && (i >> 11) == ib) b = i & 2047; }
            if (b >= 0) atomicAdd(&sh[b], 1u);
        }
    }
    __syncthreads();
    for (int i = threadIdx.x; i < 2048; i += blockDim.x) {
        unsigned vv = sh[i];
        if (vv) atomicAdd(&g_hist[phase][i], vv);
    }
}

// ---------------- selection: scan + pick bucket (R1 verbatim) ----------------
__global__ void k_scan(int phase) {
    __shared__ unsigned sA[2048], sB[2048];
    if (phase >= 3 && g_ctrl.skip) return;
    int n   = (phase == 2 || phase == 3) ? 1024 : 2048;
    int tid = threadIdx.x;  // blockDim = 1024
    const unsigned* hist = g_hist[phase];
    for (int i = tid; i < n; i += 1024) sA[i] = hist[i];
    __syncthreads();
    bool desc = (phase <= 2);
    unsigned *in = sA, *out = sB;
    for (int off = 1; off < n; off <<= 1) {
        for (int i = tid; i < n; i += 1024) {
            unsigned add = 0;
            if (desc) { if (i + off < n) add = in[i + off]; }
            else      { if (i >= off)    add = in[i - off]; }
            out[i] = in[i] + add;
        }
        __syncthreads();
        unsigned* t = in; in = out; out = t;
    }
    int rank = (phase == 0) ? K_KEEP : g_ctrl.rank;
    for (int i = tid; i < n; i += 1024) {
        bool hit;
        unsigned adj;
        if (desc) {
            unsigned nxt = (i + 1 < n) ? in[i + 1] : 0u;
            hit = ((int)in[i] >= rank) && ((int)nxt < rank);
            adj = nxt;
        } else {
            unsigned prv = (i > 0) ? in[i - 1] : 0u;
            hit = ((int)in[i] >= rank) && ((int)prv < rank);
            adj = prv;
        }
        if (hit) {
            if (phase == 0)      { g_ctrl.p1 = (unsigned)i; g_ctrl.rank = rank - (int)adj; }
            else if (phase == 1) { g_ctrl.p2 = (g_ctrl.p1 << 11) | (unsigned)i; g_ctrl.rank = rank - (int)adj; }
            else if (phase == 2) {
                g_ctrl.Tbits = (g_ctrl.p2 << 10) | (unsigned)i;
                int r   = rank - (int)adj;
                int neq = (int)(in[i] - adj);
                if (r >= neq) { g_ctrl.skip = 1; g_ctrl.cutoff = 0x7fffffff; }
                else          { g_ctrl.skip = 0; g_ctrl.rank = r; }
            }
            else if (phase == 3) { g_ctrl.ib = i; g_ctrl.rank = rank - (int)adj; }
            else                 { g_ctrl.cutoff = (g_ctrl.ib << 11) | i; }
        }
    }
}

// ---------------- hard/soft mask + edge soft sums (vectorized, guarded red) ----------------
__global__ void k_mask(const int* __restrict__ E, const float* __restrict__ probs,
                       float* __restrict__ soft, float* __restrict__ hard) {
    int t = blockIdx.x * blockDim.x + threadIdx.x;
    if (t >= NNZ / 4) return;
    float4 p4 = reinterpret_cast<const float4*>(probs)[t];
    int4   e4 = reinterpret_cast<const int4*>(E)[t];
    unsigned T = g_ctrl.Tbits;
    int cut = g_ctrl.cutoff;
    int base = t * 4;
    float pv[4] = {p4.x, p4.y, p4.z, p4.w};
    int   ev[4] = {e4.x, e4.y, e4.z, e4.w};
    float sf[4], hf[4];
#pragma unroll
    for (int j = 0; j < 4; j++) {
        unsigned bits = __float_as_uint(pv[j]);
        bool h = (bits > T) || (bits == T && (base + j) <= cut);
        hf[j] = h ? 1.0f : 0.0f;
        sf[j] = h ? ((1.0f - pv[j]) + pv[j]) : 0.0f;
        if (h)
            asm volatile("red.global.add.f32 [%0], %1;"
                         :: "l"(&g_sum_s[ev[j]]), "f"(sf[j]) : "memory");
    }
    reinterpret_cast<float4*>(soft)[t] = make_float4(sf[0], sf[1], sf[2], sf[3]);
    reinterpret_cast<float4*>(hard)[t] = make_float4(hf[0], hf[1], hf[2], hf[3]);
}

// ---------------- edge outputs (R1 verbatim) ----------------
__global__ void k_edges(float* __restrict__ ep, float* __restrict__ es, float* __restrict__ eh) {
    int e = blockIdx.x * blockDim.x + threadIdx.x;
    if (e >= N_EDGES) return;
    int ci = g_cnt[e];
    float c = (float)(ci > 1 ? ci : 1);
    float ss = g_sum_s[e];
    ep[e] = g_sum_p[e] / c;
    es[e] = ss / c;
    eh[e] = (ss > 0.0f) ? 1.0f : 0.0f;
}

// ---------------- launcher ----------------
extern "C" void kernel_launch(void* const* d_in, const int* in_sizes, int n_in,
                              void* d_out, int out_size) {
    const float* x  = (const float*)d_in[0];
    const int*   V  = (const int*)d_in[1];
    const int*   E  = (const int*)d_in[2];
    const float* W1 = (const float*)d_in[3];
    const float* b1 = (const float*)d_in[4];
    const float* W2 = (const float*)d_in[5];
    const float* b2 = (const float*)d_in[6];

    float* out   = (float*)d_out;
    float* probs = out;
    float* soft  = out + NNZ;
    float* hard  = out + 2 * NNZ;
    float* ep    = out + 3 * NNZ;
    float* es    = ep + N_EDGES;
    float* eh    = es + N_EDGES;

    k_zero<<<512, 256>>>();                                          // 1
    k_proj<<<512, 256>>>(x, W1, b1);                                 // 2
    k_scatter<<<(NNZ * 8 + 255) / 256, 256>>>(V, E);                 // 3
    k_logits<<<(NNZ * 4 + 255) / 256, 256>>>(V, E, W2, b2, probs);   // 4 <- profiled
    for (int ph = 0; ph < 5; ph++) {
        k_hist<<<512, 256>>>(probs, ph);
        k_scan<<<1, 1024>>>(ph);
    }
    k_mask<<<(NNZ / 4 + 255) / 256, 256>>>(E, probs, soft, hard);
    k_edges<<<(N_EDGES + 255) / 256, 256>>>(ep, es, eh);
}

// round 15
// speedup vs baseline: 2.4418x; 1.0379x over previous
#include <cuda_runtime.h>
#include <cstdint>
#include <math.h>

#define N_NODES   100000
#define N_EDGES   200000
#define NNZ       2000000
#define DIM       64
#define HID       32
#define K_KEEP    1000000

// ---------------- device scratch (no allocations allowed) ----------------
struct Ctrl {
    unsigned p1, p2, Tbits;
    int rank;
    int skip;
    int ib;
    int cutoff;
};

__device__ __align__(16) float g_xa[N_NODES * HID];   // x @ W1[:64] + b1
__device__ __align__(16) float g_xb[N_NODES * HID];   // x @ W1[64:]
__device__ __align__(16) float g_eb[N_EDGES * HID];   // segment sums of xb
__device__ int      g_cnt[N_EDGES];
__device__ float    g_sum_p[N_EDGES];
__device__ float    g_sum_s[N_EDGES];
__device__ unsigned g_hist[5][2048];
__device__ Ctrl     g_ctrl;

// ---------------- zero scratch (vectorized) ----------------
__global__ void k_zero() {
    int tid = blockIdx.x * blockDim.x + threadIdx.x;
    int nt  = gridDim.x * blockDim.x;
    float4 z4 = make_float4(0.f, 0.f, 0.f, 0.f);
    float4* eb4 = reinterpret_cast<float4*>(g_eb);
    for (int i = tid; i < N_EDGES * HID / 4; i += nt) eb4[i] = z4;
    for (int i = tid; i < N_EDGES; i += nt) {
        g_cnt[i] = 0; g_sum_p[i] = 0.0f; g_sum_s[i] = 0.0f;
    }
    for (int i = tid; i < 5 * 2048; i += nt) ((unsigned*)g_hist)[i] = 0u;
    if (tid == 0) {
        g_ctrl.p1 = 0; g_ctrl.p2 = 0; g_ctrl.Tbits = 0;
        g_ctrl.rank = 0; g_ctrl.skip = 0; g_ctrl.ib = 0; g_ctrl.cutoff = 0;
    }
}

// ---------------- per-node projections: xa = x@W1a + b1, xb = x@W1b ----------------
__global__ void k_proj(const float* __restrict__ x,
                       const float* __restrict__ W1,
                       const float* __restrict__ b1) {
    __shared__ float sW[128 * 32];
    for (int i = threadIdx.x; i < 128 * 32; i += blockDim.x) sW[i] = W1[i];
    __syncthreads();
    int lane = threadIdx.x & 31;
    int warp = threadIdx.x >> 5;
    int wpb  = blockDim.x >> 5;
    float bb = b1[lane];
    for (int row = blockIdx.x * wpb + warp; row < N_NODES; row += gridDim.x * wpb) {
        float x0 = x[row * 64 + lane];
        float x1 = x[row * 64 + 32 + lane];
        float aa = bb, ab = 0.0f;
#pragma unroll
        for (int k = 0; k < 32; k++) {
            float xv = __shfl_sync(0xffffffffu, x0, k);
            aa += xv * sW[k * 32 + lane];
            ab += xv * sW[(64 + k) * 32 + lane];
        }
#pragma unroll
        for (int k = 0; k < 32; k++) {
            float xv = __shfl_sync(0xffffffffu, x1, k);
            aa += xv * sW[(32 + k) * 32 + lane];
            ab += xv * sW[(96 + k) * 32 + lane];
        }
        g_xa[row * 32 + lane] = aa;
        g_xb[row * 32 + lane] = ab;
    }
}

// ---------------- scatter: 2 nnz / thread, 8 lanes / nnz, front-batched (MLP=2) ----------------
__global__ void k_scatter(const int* __restrict__ V, const int* __restrict__ E) {
    int tid = blockIdx.x * blockDim.x + threadIdx.x;
    int g0  = (tid >> 3) * 2;
    int sub = tid & 7;
    if (g0 >= NNZ) return;
    int g1 = g0 + 1;
    // front-batch all independent loads
    int v0 = V[g0], e0 = E[g0];
    int v1 = V[g1], e1 = E[g1];
    float4 val0 = *reinterpret_cast<const float4*>(&g_xb[v0 * 32 + sub * 4]);
    float4 val1 = *reinterpret_cast<const float4*>(&g_xb[v1 * 32 + sub * 4]);
    float* dst0 = &g_eb[e0 * 32 + sub * 4];
    float* dst1 = &g_eb[e1 * 32 + sub * 4];
    asm volatile("red.global.add.v4.f32 [%0], {%1,%2,%3,%4};"
                 :: "l"(dst0), "f"(val0.x), "f"(val0.y), "f"(val0.z), "f"(val0.w)
                 : "memory");
    asm volatile("red.global.add.v4.f32 [%0], {%1,%2,%3,%4};"
                 :: "l"(dst1), "f"(val1.x), "f"(val1.y), "f"(val1.z), "f"(val1.w)
                 : "memory");
    if (sub == 0) {
        atomicAdd(&g_cnt[e0], 1);
        atomicAdd(&g_cnt[e1], 1);
    }
}

// ---------------- fused MLP: probs + edge prob sums (4 lanes / nnz) ----------------
__global__ void k_logits(const int* __restrict__ V, const int* __restrict__ E,
                         const float* __restrict__ W2, const float* __restrict__ b2,
                         float* __restrict__ out_probs) {
    int tid = blockIdx.x * blockDim.x + threadIdx.x;
    int g   = tid >> 2;
    int sub = tid & 3;
    if (g >= NNZ) return;
    int v = V[g], e = E[g];
    int c = g_cnt[e];
    float ic = 1.0f / (float)(c > 1 ? c : 1);
    const float4* pa = reinterpret_cast<const float4*>(&g_xa[v * 32]) + sub * 2;
    const float4* pm = reinterpret_cast<const float4*>(&g_eb[e * 32]) + sub * 2;
    const float4* pw = reinterpret_cast<const float4*>(W2) + sub * 2;
    float4 a0 = pa[0], a1 = pa[1];
    float4 m0 = pm[0], m1 = pm[1];
    float4 w0 = pw[0], w1 = pw[1];
    float part =
        fmaxf(a0.x + m0.x * ic, 0.0f) * w0.x +
        fmaxf(a0.y + m0.y * ic, 0.0f) * w0.y +
        fmaxf(a0.z + m0.z * ic, 0.0f) * w0.z +
        fmaxf(a0.w + m0.w * ic, 0.0f) * w0.w +
        fmaxf(a1.x + m1.x * ic, 0.0f) * w1.x +
        fmaxf(a1.y + m1.y * ic, 0.0f) * w1.y +
        fmaxf(a1.z + m1.z * ic, 0.0f) * w1.z +
        fmaxf(a1.w + m1.w * ic, 0.0f) * w1.w;
    part += __shfl_xor_sync(0xffffffffu, part, 2);
    part += __shfl_xor_sync(0xffffffffu, part, 1);
    if (sub == 0) {
        float z = part + b2[0];
        float p = 1.0f / (1.0f + __expf(-z));
        out_probs[g] = p;
        asm volatile("red.global.add.f32 [%0], %1;" :: "l"(&g_sum_p[e]), "f"(p) : "memory");
    }
}

// ---------------- selection: histograms (vectorized float4 loads) ----------------
__global__ void k_hist(const float* __restrict__ probs, int phase) {
    __shared__ unsigned sh[2048];
    for (int i = threadIdx.x; i < 2048; i += blockDim.x) sh[i] = 0u;
    __syncthreads();
    unsigned p1 = g_ctrl.p1, p2 = g_ctrl.p2, Tb = g_ctrl.Tbits;
    int ib = g_ctrl.ib, skip = g_ctrl.skip;
    if (phase >= 3 && skip) return;   // uniform across all threads
    int tid = blockIdx.x * blockDim.x + threadIdx.x;
    int nt  = gridDim.x * blockDim.x;
    for (int t = tid; t < NNZ / 4; t += nt) {
        float4 p4 = reinterpret_cast<const float4*>(probs)[t];
        float pv[4] = {p4.x, p4.y, p4.z, p4.w};
#pragma unroll
        for (int j = 0; j < 4; j++) {
            unsigned bits = __float_as_uint(pv[j]);
            int i = 4 * t + j;
            int b = -1;
            if (phase == 0)      b = (int)(bits >> 21);
            else if (phase == 1) { if ((bits >> 21) == p1) b = (int)((bits >> 10) & 2047u); }
            else if (phase == 2) { if ((bits >> 10) == p2) b = (int)(bits & 1023u); }
            else if (phase == 3) { if (bits == Tb) b = i >> 11; }
            else                 { if (bits == Tb && (i >> 11) == ib) b = i & 2047; }
            if (b >= 0) atomicAdd(&sh[b], 1u);
        }
    }
    __syncthreads();
    for (int i = threadIdx.x; i < 2048; i += blockDim.x) {
        unsigned vv = sh[i];
        if (vv) atomicAdd(&g_hist[phase][i], vv);
    }
}

// ---------------- selection: scan + pick bucket (R1 verbatim) ----------------
__global__ void k_scan(int phase) {
    __shared__ unsigned sA[2048], sB[2048];
    if (phase >= 3 && g_ctrl.skip) return;
    int n   = (phase == 2 || phase == 3) ? 1024 : 2048;
    int tid = threadIdx.x;  // blockDim = 1024
    const unsigned* hist = g_hist[phase];
    for (int i = tid; i < n; i += 1024) sA[i] = hist[i];
    __syncthreads();
    bool desc = (phase <= 2);
    unsigned *in = sA, *out = sB;
    for (int off = 1; off < n; off <<= 1) {
        for (int i = tid; i < n; i += 1024) {
            unsigned add = 0;
            if (desc) { if (i + off < n) add = in[i + off]; }
            else      { if (i >= off)    add = in[i - off]; }
            out[i] = in[i] + add;
        }
        __syncthreads();
        unsigned* t = in; in = out; out = t;
    }
    int rank = (phase == 0) ? K_KEEP : g_ctrl.rank;
    for (int i = tid; i < n; i += 1024) {
        bool hit;
        unsigned adj;
        if (desc) {
            unsigned nxt = (i + 1 < n) ? in[i + 1] : 0u;
            hit = ((int)in[i] >= rank) && ((int)nxt < rank);
            adj = nxt;
        } else {
            unsigned prv = (i > 0) ? in[i - 1] : 0u;
            hit = ((int)in[i] >= rank) && ((int)prv < rank);
            adj = prv;
        }
        if (hit) {
            if (phase == 0)      { g_ctrl.p1 = (unsigned)i; g_ctrl.rank = rank - (int)adj; }
            else if (phase == 1) { g_ctrl.p2 = (g_ctrl.p1 << 11) | (unsigned)i; g_ctrl.rank = rank - (int)adj; }
            else if (phase == 2) {
                g_ctrl.Tbits = (g_ctrl.p2 << 10) | (unsigned)i;
                int r   = rank - (int)adj;
                int neq = (int)(in[i] - adj);
                if (r >= neq) { g_ctrl.skip = 1; g_ctrl.cutoff = 0x7fffffff; }
                else          { g_ctrl.skip = 0; g_ctrl.rank = r; }
            }
            else if (phase == 3) { g_ctrl.ib = i; g_ctrl.rank = rank - (int)adj; }
            else                 { g_ctrl.cutoff = (g_ctrl.ib << 11) | i; }
        }
    }
}

// ---------------- hard/soft mask + edge soft sums (vectorized, guarded red) ----------------
__global__ void k_mask(const int* __restrict__ E, const float* __restrict__ probs,
                       float* __restrict__ soft, float* __restrict__ hard) {
    int t = blockIdx.x * blockDim.x + threadIdx.x;
    if (t >= NNZ / 4) return;
    float4 p4 = reinterpret_cast<const float4*>(probs)[t];
    int4   e4 = reinterpret_cast<const int4*>(E)[t];
    unsigned T = g_ctrl.Tbits;
    int cut = g_ctrl.cutoff;
    int base = t * 4;
    float pv[4] = {p4.x, p4.y, p4.z, p4.w};
    int   ev[4] = {e4.x, e4.y, e4.z, e4.w};
    float sf[4], hf[4];
#pragma unroll
    for (int j = 0; j < 4; j++) {
        unsigned bits = __float_as_uint(pv[j]);
        bool h = (bits > T) || (bits == T && (base + j) <= cut);
        hf[j] = h ? 1.0f : 0.0f;
        sf[j] = h ? ((1.0f - pv[j]) + pv[j]) : 0.0f;
        if (h)
            asm volatile("red.global.add.f32 [%0], %1;"
                         :: "l"(&g_sum_s[ev[j]]), "f"(sf[j]) : "memory");
    }
    reinterpret_cast<float4*>(soft)[t] = make_float4(sf[0], sf[1], sf[2], sf[3]);
    reinterpret_cast<float4*>(hard)[t] = make_float4(hf[0], hf[1], hf[2], hf[3]);
}

// ---------------- edge outputs (vectorized) ----------------
__global__ void k_edges(float* __restrict__ ep, float* __restrict__ es, float* __restrict__ eh) {
    int t = blockIdx.x * blockDim.x + threadIdx.x;
    if (t >= N_EDGES / 4) return;
    int4   c4 = reinterpret_cast<const int4*>(g_cnt)[t];
    float4 sp = reinterpret_cast<const float4*>(g_sum_p)[t];
    float4 ss = reinterpret_cast<const float4*>(g_sum_s)[t];
    float c0 = (float)(c4.x > 1 ? c4.x : 1);
    float c1 = (float)(c4.y > 1 ? c4.y : 1);
    float c2 = (float)(c4.z > 1 ? c4.z : 1);
    float c3 = (float)(c4.w > 1 ? c4.w : 1);
    reinterpret_cast<float4*>(ep)[t] = make_float4(sp.x / c0, sp.y / c1, sp.z / c2, sp.w / c3);
    reinterpret_cast<float4*>(es)[t] = make_float4(ss.x / c0, ss.y / c1, ss.z / c2, ss.w / c3);
    reinterpret_cast<float4*>(eh)[t] = make_float4(ss.x > 0.f ? 1.f : 0.f, ss.y > 0.f ? 1.f : 0.f,
                                                   ss.z > 0.f ? 1.f : 0.f, ss.w > 0.f ? 1.f : 0.f);
}

// ---------------- launcher ----------------
extern "C" void kernel_launch(void* const* d_in, const int* in_sizes, int n_in,
                              void* d_out, int out_size) {
    const float* x  = (const float*)d_in[0];
    const int*   V  = (const int*)d_in[1];
    const int*   E  = (const int*)d_in[2];
    const float* W1 = (const float*)d_in[3];
    const float* b1 = (const float*)d_in[4];
    const float* W2 = (const float*)d_in[5];
    const float* b2 = (const float*)d_in[6];

    float* out   = (float*)d_out;
    float* probs = out;
    float* soft  = out + NNZ;
    float* hard  = out + 2 * NNZ;
    float* ep    = out + 3 * NNZ;
    float* es    = ep + N_EDGES;
    float* eh    = es + N_EDGES;

    k_zero<<<512, 256>>>();                                          // 1
    k_proj<<<512, 256>>>(x, W1, b1);                                 // 2
    k_scatter<<<(NNZ * 4 + 255) / 256, 256>>>(V, E);                 // 3 <- 2 nnz/thread
    k_logits<<<(NNZ * 4 + 255) / 256, 256>>>(V, E, W2, b2, probs);   // 4 <- profiled
    for (int ph = 0; ph < 5; ph++) {
        k_hist<<<512, 256>>>(probs, ph);
        k_scan<<<1, 1024>>>(ph);
    }
    k_mask<<<(NNZ / 4 + 255) / 256, 256>>>(E, probs, soft, hard);
    k_edges<<<(N_EDGES / 4 + 255) / 256, 256>>>(ep, es, eh);
}

// round 16
// speedup vs baseline: 2.4613x; 1.0080x over previous
#include <cuda_runtime.h>
#include <cstdint>
#include <math.h>

#define N_NODES   100000
#define N_EDGES   200000
#define NNZ       2000000
#define DIM       64
#define HID       32
#define K_KEEP    1000000

// ---------------- device scratch (no allocations allowed) ----------------
struct Ctrl {
    unsigned p1, p2, Tbits;
    int rank;
    int skip;
    int ib;
    int cutoff;
};

__device__ __align__(16) float g_xa[N_NODES * HID];   // x @ W1[:64] + b1
__device__ __align__(16) float g_xb[N_NODES * HID];   // x @ W1[64:]
__device__ __align__(16) float g_eb[N_EDGES * HID];   // segment sums of xb
__device__ int      g_cnt[N_EDGES];
__device__ float    g_sum_p[N_EDGES];
__device__ float    g_sum_s[N_EDGES];
__device__ unsigned g_hist[5][2048];
__device__ Ctrl     g_ctrl;

// ---------------- zero scratch (vectorized) ----------------
__global__ void k_zero() {
    int tid = blockIdx.x * blockDim.x + threadIdx.x;
    int nt  = gridDim.x * blockDim.x;
    float4 z4 = make_float4(0.f, 0.f, 0.f, 0.f);
    float4* eb4 = reinterpret_cast<float4*>(g_eb);
    for (int i = tid; i < N_EDGES * HID / 4; i += nt) eb4[i] = z4;
    for (int i = tid; i < N_EDGES; i += nt) {
        g_cnt[i] = 0; g_sum_p[i] = 0.0f; g_sum_s[i] = 0.0f;
    }
    for (int i = tid; i < 5 * 2048; i += nt) ((unsigned*)g_hist)[i] = 0u;
    if (tid == 0) {
        g_ctrl.p1 = 0; g_ctrl.p2 = 0; g_ctrl.Tbits = 0;
        g_ctrl.rank = 0; g_ctrl.skip = 0; g_ctrl.ib = 0; g_ctrl.cutoff = 0;
    }
}

// ---------------- per-node projections: xa = x@W1a + b1, xb = x@W1b ----------------
__global__ void k_proj(const float* __restrict__ x,
                       const float* __restrict__ W1,
                       const float* __restrict__ b1) {
    __shared__ float sW[128 * 32];
    for (int i = threadIdx.x; i < 128 * 32; i += blockDim.x) sW[i] = W1[i];
    __syncthreads();
    int lane = threadIdx.x & 31;
    int warp = threadIdx.x >> 5;
    int wpb  = blockDim.x >> 5;
    float bb = b1[lane];
    for (int row = blockIdx.x * wpb + warp; row < N_NODES; row += gridDim.x * wpb) {
        float x0 = x[row * 64 + lane];
        float x1 = x[row * 64 + 32 + lane];
        float aa = bb, ab = 0.0f;
#pragma unroll
        for (int k = 0; k < 32; k++) {
            float xv = __shfl_sync(0xffffffffu, x0, k);
            aa += xv * sW[k * 32 + lane];
            ab += xv * sW[(64 + k) * 32 + lane];
        }
#pragma unroll
        for (int k = 0; k < 32; k++) {
            float xv = __shfl_sync(0xffffffffu, x1, k);
            aa += xv * sW[(32 + k) * 32 + lane];
            ab += xv * sW[(96 + k) * 32 + lane];
        }
        g_xa[row * 32 + lane] = aa;
        g_xb[row * 32 + lane] = ab;
    }
}

// ---------------- scatter: 4 nnz / thread, 8 lanes / nnz, int4 index loads, MLP=4 ----------------
__global__ void k_scatter(const int* __restrict__ V, const int* __restrict__ E) {
    int tid = blockIdx.x * blockDim.x + threadIdx.x;
    int g0  = (tid >> 3) * 4;
    int sub = tid & 7;
    if (g0 >= NNZ) return;
    int4 v4 = *reinterpret_cast<const int4*>(&V[g0]);
    int4 e4 = *reinterpret_cast<const int4*>(&E[g0]);
    // front-batch all 4 gathers (independent -> MLP=4)
    float4 a = *reinterpret_cast<const float4*>(&g_xb[v4.x * 32 + sub * 4]);
    float4 b = *reinterpret_cast<const float4*>(&g_xb[v4.y * 32 + sub * 4]);
    float4 c = *reinterpret_cast<const float4*>(&g_xb[v4.z * 32 + sub * 4]);
    float4 d = *reinterpret_cast<const float4*>(&g_xb[v4.w * 32 + sub * 4]);
    asm volatile("red.global.add.v4.f32 [%0], {%1,%2,%3,%4};"
                 :: "l"(&g_eb[e4.x * 32 + sub * 4]), "f"(a.x), "f"(a.y), "f"(a.z), "f"(a.w) : "memory");
    asm volatile("red.global.add.v4.f32 [%0], {%1,%2,%3,%4};"
                 :: "l"(&g_eb[e4.y * 32 + sub * 4]), "f"(b.x), "f"(b.y), "f"(b.z), "f"(b.w) : "memory");
    asm volatile("red.global.add.v4.f32 [%0], {%1,%2,%3,%4};"
                 :: "l"(&g_eb[e4.z * 32 + sub * 4]), "f"(c.x), "f"(c.y), "f"(c.z), "f"(c.w) : "memory");
    asm volatile("red.global.add.v4.f32 [%0], {%1,%2,%3,%4};"
                 :: "l"(&g_eb[e4.w * 32 + sub * 4]), "f"(d.x), "f"(d.y), "f"(d.z), "f"(d.w) : "memory");
    if (sub == 0) {
        atomicAdd(&g_cnt[e4.x], 1);
        atomicAdd(&g_cnt[e4.y], 1);
        atomicAdd(&g_cnt[e4.z], 1);
        atomicAdd(&g_cnt[e4.w], 1);
    }
}

// ---------------- fused MLP: probs + edge prob sums (4 lanes / nnz) ----------------
__global__ void k_logits(const int* __restrict__ V, const int* __restrict__ E,
                         const float* __restrict__ W2, const float* __restrict__ b2,
                         float* __restrict__ out_probs) {
    int tid = blockIdx.x * blockDim.x + threadIdx.x;
    int g   = tid >> 2;
    int sub = tid & 3;
    if (g >= NNZ) return;
    int v = V[g], e = E[g];
    int c = g_cnt[e];
    float ic = 1.0f / (float)(c > 1 ? c : 1);
    const float4* pa = reinterpret_cast<const float4*>(&g_xa[v * 32]) + sub * 2;
    const float4* pm = reinterpret_cast<const float4*>(&g_eb[e * 32]) + sub * 2;
    const float4* pw = reinterpret_cast<const float4*>(W2) + sub * 2;
    float4 a0 = pa[0], a1 = pa[1];
    float4 m0 = pm[0], m1 = pm[1];
    float4 w0 = pw[0], w1 = pw[1];
    float part =
        fmaxf(a0.x + m0.x * ic, 0.0f) * w0.x +
        fmaxf(a0.y + m0.y * ic, 0.0f) * w0.y +
        fmaxf(a0.z + m0.z * ic, 0.0f) * w0.z +
        fmaxf(a0.w + m0.w * ic, 0.0f) * w0.w +
        fmaxf(a1.x + m1.x * ic, 0.0f) * w1.x +
        fmaxf(a1.y + m1.y * ic, 0.0f) * w1.y +
        fmaxf(a1.z + m1.z * ic, 0.0f) * w1.z +
        fmaxf(a1.w + m1.w * ic, 0.0f) * w1.w;
    part += __shfl_xor_sync(0xffffffffu, part, 2);
    part += __shfl_xor_sync(0xffffffffu, part, 1);
    if (sub == 0) {
        float z = part + b2[0];
        float p = 1.0f / (1.0f + __expf(-z));
        out_probs[g] = p;
        asm volatile("red.global.add.f32 [%0], %1;" :: "l"(&g_sum_p[e]), "f"(p) : "memory");
    }
}

// ---------------- selection: histograms (vectorized float4 loads) ----------------
__global__ void k_hist(const float* __restrict__ probs, int phase) {
    __shared__ unsigned sh[2048];
    for (int i = threadIdx.x; i < 2048; i += blockDim.x) sh[i] = 0u;
    __syncthreads();
    unsigned p1 = g_ctrl.p1, p2 = g_ctrl.p2, Tb = g_ctrl.Tbits;
    int ib = g_ctrl.ib, skip = g_ctrl.skip;
    if (phase >= 3 && skip) return;   // uniform across all threads
    int tid = blockIdx.x * blockDim.x + threadIdx.x;
    int nt  = gridDim.x * blockDim.x;
    for (int t = tid; t < NNZ / 4; t += nt) {
        float4 p4 = reinterpret_cast<const float4*>(probs)[t];
        float pv[4] = {p4.x, p4.y, p4.z, p4.w};
#pragma unroll
        for (int j = 0; j < 4; j++) {
            unsigned bits = __float_as_uint(pv[j]);
            int i = 4 * t + j;
            int b = -1;
            if (phase == 0)      b = (int)(bits >> 21);
            else if (phase == 1) { if ((bits >> 21) == p1) b = (int)((bits >> 10) & 2047u); }
            else if (phase == 2) { if ((bits >> 10) == p2) b = (int)(bits & 1023u); }
            else if (phase == 3) { if (bits == Tb) b = i >> 11; }
            else                 { if (bits == Tb && (i >> 11) == ib) b = i & 2047; }
            if (b >= 0) atomicAdd(&sh[b], 1u);
        }
    }
    __syncthreads();
    for (int i = threadIdx.x; i < 2048; i += blockDim.x) {
        unsigned vv = sh[i];
        if (vv) atomicAdd(&g_hist[phase][i], vv);
    }
}

// ---------------- selection: scan + pick bucket (R1 verbatim) ----------------
__global__ void k_scan(int phase) {
    __shared__ unsigned sA[2048], sB[2048];
    if (phase >= 3 && g_ctrl.skip) return;
    int n   = (phase == 2 || phase == 3) ? 1024 : 2048;
    int tid = threadIdx.x;  // blockDim = 1024
    const unsigned* hist = g_hist[phase];
    for (int i = tid; i < n; i += 1024) sA[i] = hist[i];
    __syncthreads();
    bool desc = (phase <= 2);
    unsigned *in = sA, *out = sB;
    for (int off = 1; off < n; off <<= 1) {
        for (int i = tid; i < n; i += 1024) {
            unsigned add = 0;
            if (desc) { if (i + off < n) add = in[i + off]; }
            else      { if (i >= off)    add = in[i - off]; }
            out[i] = in[i] + add;
        }
        __syncthreads();
        unsigned* t = in; in = out; out = t;
    }
    int rank = (phase == 0) ? K_KEEP : g_ctrl.rank;
    for (int i = tid; i < n; i += 1024) {
        bool hit;
        unsigned adj;
        if (desc) {
            unsigned nxt = (i + 1 < n) ? in[i + 1] : 0u;
            hit = ((int)in[i] >= rank) && ((int)nxt < rank);
            adj = nxt;
        } else {
            unsigned prv = (i > 0) ? in[i - 1] : 0u;
            hit = ((int)in[i] >= rank) && ((int)prv < rank);
            adj = prv;
        }
        if (hit) {
            if (phase == 0)      { g_ctrl.p1 = (unsigned)i; g_ctrl.rank = rank - (int)adj; }
            else if (phase == 1) { g_ctrl.p2 = (g_ctrl.p1 << 11) | (unsigned)i; g_ctrl.rank = rank - (int)adj; }
            else if (phase == 2) {
                g_ctrl.Tbits = (g_ctrl.p2 << 10) | (unsigned)i;
                int r   = rank - (int)adj;
                int neq = (int)(in[i] - adj);
                if (r >= neq) { g_ctrl.skip = 1; g_ctrl.cutoff = 0x7fffffff; }
                else          { g_ctrl.skip = 0; g_ctrl.rank = r; }
            }
            else if (phase == 3) { g_ctrl.ib = i; g_ctrl.rank = rank - (int)adj; }
            else                 { g_ctrl.cutoff = (g_ctrl.ib << 11) | i; }
        }
    }
}

// ---------------- hard/soft mask + edge soft sums (vectorized, guarded red) ----------------
__global__ void k_mask(const int* __restrict__ E, const float* __restrict__ probs,
                       float* __restrict__ soft, float* __restrict__ hard) {
    int t = blockIdx.x * blockDim.x + threadIdx.x;
    if (t >= NNZ / 4) return;
    float4 p4 = reinterpret_cast<const float4*>(probs)[t];
    int4   e4 = reinterpret_cast<const int4*>(E)[t];
    unsigned T = g_ctrl.Tbits;
    int cut = g_ctrl.cutoff;
    int base = t * 4;
    float pv[4] = {p4.x, p4.y, p4.z, p4.w};
    int   ev[4] = {e4.x, e4.y, e4.z, e4.w};
    float sf[4], hf[4];
#pragma unroll
    for (int j = 0; j < 4; j++) {
        unsigned bits = __float_as_uint(pv[j]);
        bool h = (bits > T) || (bits == T && (base + j) <= cut);
        hf[j] = h ? 1.0f : 0.0f;
        sf[j] = h ? ((1.0f - pv[j]) + pv[j]) : 0.0f;
        if (h)
            asm volatile("red.global.add.f32 [%0], %1;"
                         :: "l"(&g_sum_s[ev[j]]), "f"(sf[j]) : "memory");
    }
    reinterpret_cast<float4*>(soft)[t] = make_float4(sf[0], sf[1], sf[2], sf[3]);
    reinterpret_cast<float4*>(hard)[t] = make_float4(hf[0], hf[1], hf[2], hf[3]);
}

// ---------------- edge outputs (vectorized) ----------------
__global__ void k_edges(float* __restrict__ ep, float* __restrict__ es, float* __restrict__ eh) {
    int t = blockIdx.x * blockDim.x + threadIdx.x;
    if (t >= N_EDGES / 4) return;
    int4   c4 = reinterpret_cast<const int4*>(g_cnt)[t];
    float4 sp = reinterpret_cast<const float4*>(g_sum_p)[t];
    float4 ss = reinterpret_cast<const float4*>(g_sum_s)[t];
    float c0 = (float)(c4.x > 1 ? c4.x : 1);
    float c1 = (float)(c4.y > 1 ? c4.y : 1);
    float c2 = (float)(c4.z > 1 ? c4.z : 1);
    float c3 = (float)(c4.w > 1 ? c4.w : 1);
    reinterpret_cast<float4*>(ep)[t] = make_float4(sp.x / c0, sp.y / c1, sp.z / c2, sp.w / c3);
    reinterpret_cast<float4*>(es)[t] = make_float4(ss.x / c0, ss.y / c1, ss.z / c2, ss.w / c3);
    reinterpret_cast<float4*>(eh)[t] = make_float4(ss.x > 0.f ? 1.f : 0.f, ss.y > 0.f ? 1.f : 0.f,
                                                   ss.z > 0.f ? 1.f : 0.f, ss.w > 0.f ? 1.f : 0.f);
}

// ---------------- launcher ----------------
extern "C" void kernel_launch(void* const* d_in, const int* in_sizes, int n_in,
                              void* d_out, int out_size) {
    const float* x  = (const float*)d_in[0];
    const int*   V  = (const int*)d_in[1];
    const int*   E  = (const int*)d_in[2];
    const float* W1 = (const float*)d_in[3];
    const float* b1 = (const float*)d_in[4];
    const float* W2 = (const float*)d_in[5];
    const float* b2 = (const float*)d_in[6];

    float* out   = (float*)d_out;
    float* probs = out;
    float* soft  = out + NNZ;
    float* hard  = out + 2 * NNZ;
    float* ep    = out + 3 * NNZ;
    float* es    = ep + N_EDGES;
    float* eh    = es + N_EDGES;

    k_zero<<<512, 256>>>();                                          // 1
    k_proj<<<512, 256>>>(x, W1, b1);                                 // 2
    k_scatter<<<(NNZ * 2 + 255) / 256, 256>>>(V, E);                 // 3 <- 4 nnz/thread
    k_logits<<<(NNZ * 4 + 255) / 256, 256>>>(V, E, W2, b2, probs);   // 4 <- profiled
    for (int ph = 0; ph < 5; ph++) {
        k_hist<<<512, 256>>>(probs, ph);
        k_scan<<<1, 1024>>>(ph);
    }
    k_mask<<<(NNZ / 4 + 255) / 256, 256>>>(E, probs, soft, hard);
    k_edges<<<(N_EDGES / 4 + 255) / 256, 256>>>(ep, es, eh);
}